// round 11
// baseline (speedup 1.0000x reference)
#include <cuda_runtime.h>
#include <cuda_bf16.h>

#define BATCH 8
#define H 512
#define W 512
#define KS 5
#define PAD 2

#define TX 32
#define TY 8
#define PY 2
#define OTY (TY * PY)       // 16 output rows per block
#define SW (TX + 2*PAD)     // 36
#define SH (OTY + 2*PAD)    // 20
#define TILE_N (SH * SW)    // 720
#define NTHREADS (TX * TY)  // 256

#define CHUNKS 64           // phase-1 minmax blocks per batch

__device__ float g_pmn[BATCH * CHUNKS];
__device__ float g_pmx[BATCH * CHUNKS];

// ---------------- Kernel A: per-chunk partial min/max (plain, R8 version) ----------------
__global__ __launch_bounds__(256) void minmax_partial_kernel(const float* __restrict__ cm) {
    const int b = blockIdx.y;
    const int c = blockIdx.x;
    const float4* p = reinterpret_cast<const float4*>(cm) + ((size_t)b * (H * W / 4)) + (size_t)c * 1024;

    float mn = 1e30f, mx = -1e30f;
    #pragma unroll
    for (int i = 0; i < 4; ++i) {
        float4 v = p[threadIdx.x + i * 256];
        mn = fminf(mn, fminf(fminf(v.x, v.y), fminf(v.z, v.w)));
        mx = fmaxf(mx, fmaxf(fmaxf(v.x, v.y), fmaxf(v.z, v.w)));
    }
    #pragma unroll
    for (int o = 16; o; o >>= 1) {
        mn = fminf(mn, __shfl_xor_sync(0xFFFFFFFFu, mn, o));
        mx = fmaxf(mx, __shfl_xor_sync(0xFFFFFFFFu, mx, o));
    }
    __shared__ float smn[8], smx[8];
    const int wid = threadIdx.x >> 5, lid = threadIdx.x & 31;
    if (lid == 0) { smn[wid] = mn; smx[wid] = mx; }
    __syncthreads();
    if (threadIdx.x == 0) {
        #pragma unroll
        for (int i = 1; i < 8; ++i) { mn = fminf(mn, smn[i]); mx = fmaxf(mx, smx[i]); }
        g_pmn[b * CHUNKS + c] = mn;
        g_pmx[b * CHUNKS + c] = mx;
    }
}

// ---------------- Kernel B: sampler, single-warp prologue reduce ----------------
__global__ __launch_bounds__(NTHREADS) void sampler_kernel(
    const float* __restrict__ cm,
    const float* __restrict__ rnd,
    const float* __restrict__ kern,
    float* __restrict__ coords,   // [B,512,512,4,2]
    float* __restrict__ weights,  // [B,512,512,4]
    float* __restrict__ density)  // [B,1,512,512]
{
    __shared__ float tile[SH][SW];
    __shared__ float kw[KS * KS];
    __shared__ float s_mn, s_sc;

    const int b   = blockIdx.z;
    const int tid = threadIdx.y * TX + threadIdx.x;

    const int x   = blockIdx.x * TX + threadIdx.x;
    const int ty2 = threadIdx.y * PY;
    const int y   = blockIdx.y * OTY + ty2;

    // ---------- contrast tile prefetch (registers, 3 values) ----------
    const int x0 = blockIdx.x * TX - PAD;
    const int y0 = blockIdx.y * OTY - PAD;
    const float* cmb = cm + (size_t)b * H * W;

    float pre[3];
    bool  pok[3];
    #pragma unroll
    for (int t = 0; t < 3; ++t) {
        const int i  = tid + t * NTHREADS;
        const int ly = i / SW, lx = i - ly * SW;
        const int gy = y0 + ly, gx = x0 + lx;
        pok[t] = (i < TILE_N) && ((unsigned)gy < H) && ((unsigned)gx < W);
        pre[t] = pok[t] ? cmb[gy * W + gx] : 0.0f;
    }

    if (tid < KS * KS) kw[tid] = kern[tid];

    // ---------- single-warp reduce of 64 partials -> (mn, sc) ----------
    if (tid < 32) {
        const float* pmn = &g_pmn[b * CHUNKS];
        const float* pmx = &g_pmx[b * CHUNKS];
        float mn = fminf(pmn[tid], pmn[tid + 32]);
        float mx = fmaxf(pmx[tid], pmx[tid + 32]);
        #pragma unroll
        for (int o = 16; o; o >>= 1) {
            mn = fminf(mn, __shfl_xor_sync(0xFFFFFFFFu, mn, o));
            mx = fmaxf(mx, __shfl_xor_sync(0xFFFFFFFFu, mx, o));
        }
        if (tid == 0) {
            s_mn = mn;
            const float rng = mx - mn;
            s_sc = (rng > 0.0f) ? (1.0f / rng) : 0.0f;
        }
    }
    __syncthreads();

    const float mn = s_mn;
    const float sc = s_sc;

    // ---------- normalize prefetched tile into smem ----------
    #pragma unroll
    for (int t = 0; t < 3; ++t) {
        const int i = tid + t * NTHREADS;
        if (i < TILE_N) {
            const int ly = i / SW, lx = i - ly * SW;
            tile[ly][lx] = pok[t] ? (pre[t] - mn) * sc : 0.0f;
        }
    }
    __syncthreads();

    // ---------- rnd loads: overlap the conv, short register lifetime ----------
    const size_t pix0 = ((size_t)b * H + y) * W + x;
    const size_t pix1 = pix0 + W;
    const float4* rp0 = reinterpret_cast<const float4*>(rnd + pix0 * 8);
    const float4* rp1 = reinterpret_cast<const float4*>(rnd + pix1 * 8);
    float4 ra0 = __ldcs(rp0 + 0);
    float4 ra1 = __ldcs(rp0 + 1);
    float4 rb0 = __ldcs(rp1 + 0);
    float4 rb1 = __ldcs(rp1 + 1);

    // ---------- 5x5 conv, two adjacent rows, order-preserving ----------
    float acc0 = 0.0f, acc1 = 0.0f;
    #pragma unroll
    for (int r = 0; r < KS + 1; ++r) {
        float t0 = tile[ty2 + r][threadIdx.x + 0];
        float t1 = tile[ty2 + r][threadIdx.x + 1];
        float t2 = tile[ty2 + r][threadIdx.x + 2];
        float t3 = tile[ty2 + r][threadIdx.x + 3];
        float t4 = tile[ty2 + r][threadIdx.x + 4];
        if (r < KS) {
            acc0 = fmaf(kw[r * KS + 0], t0, acc0);
            acc0 = fmaf(kw[r * KS + 1], t1, acc0);
            acc0 = fmaf(kw[r * KS + 2], t2, acc0);
            acc0 = fmaf(kw[r * KS + 3], t3, acc0);
            acc0 = fmaf(kw[r * KS + 4], t4, acc0);
        }
        if (r > 0) {
            acc1 = fmaf(kw[(r - 1) * KS + 0], t0, acc1);
            acc1 = fmaf(kw[(r - 1) * KS + 1], t1, acc1);
            acc1 = fmaf(kw[(r - 1) * KS + 2], t2, acc1);
            acc1 = fmaf(kw[(r - 1) * KS + 3], t3, acc1);
            acc1 = fmaf(kw[(r - 1) * KS + 4], t4, acc1);
        }
    }

    // ---------- outputs ----------
    const float step = 2.0f / 511.0f;
    const float bx = fmaf((float)x, step, -1.0f);

    #pragma unroll
    for (int p = 0; p < PY; ++p) {
        const float acc = (p == 0) ? acc0 : acc1;
        const int   yy  = y + p;
        const float4 r0 = (p == 0) ? ra0 : rb0;
        const float4 r1 = (p == 0) ? ra1 : rb1;

        const float d   = fmaf(0.9f, sqrtf(acc), 0.1f);
        const int   ns  = (d > 0.7f) ? 4 : ((d > 0.4f) ? 2 : 1);
        const float by  = fmaf((float)yy, step, -1.0f);
        const float osc = (ns > 1) ? (2.0f / 512.0f * 0.8f) : 0.0f;

        const size_t pix = (p == 0) ? pix0 : pix1;

        float4 c0, c1;
        c0.x = fmaf(r0.x - 0.5f, osc, by);
        c0.y = fmaf(r0.y - 0.5f, osc, bx);
        c0.z = fmaf(r0.z - 0.5f, osc, by);
        c0.w = fmaf(r0.w - 0.5f, osc, bx);
        c1.x = fmaf(r1.x - 0.5f, osc, by);
        c1.y = fmaf(r1.y - 0.5f, osc, bx);
        c1.z = fmaf(r1.z - 0.5f, osc, by);
        c1.w = fmaf(r1.w - 0.5f, osc, bx);

        float4* cout = reinterpret_cast<float4*>(coords + pix * 8);
        cout[0] = c0;
        cout[1] = c1;

        const float wv = d / (float)ns;
        float4 wq;
        wq.x = wv;
        wq.y = (ns > 1) ? wv : 0.0f;
        wq.z = (ns > 2) ? wv : 0.0f;
        wq.w = (ns > 2) ? wv : 0.0f;
        reinterpret_cast<float4*>(weights + pix * 4)[0] = wq;

        density[pix] = d;
    }
}

extern "C" void kernel_launch(void* const* d_in, const int* in_sizes, int n_in,
                              void* d_out, int out_size) {
    const float* cm   = (const float*)d_in[0];  // [8,1,512,512]
    const float* rnd  = (const float*)d_in[1];  // [8,512,512,4,2]
    const float* kern = (const float*)d_in[2];  // [1,1,5,5]

    float* out = (float*)d_out;
    float* coords  = out;                                   // 16777216
    float* weights = out + (size_t)BATCH * H * W * 8;       //  8388608
    float* density = weights + (size_t)BATCH * H * W * 4;   //  2097152

    dim3 agrd(CHUNKS, BATCH, 1);
    minmax_partial_kernel<<<agrd, 256>>>(cm);

    dim3 blk(TX, TY, 1);
    dim3 grd(W / TX, H / OTY, BATCH);
    sampler_kernel<<<grd, blk>>>(cm, rnd, kern, coords, weights, density);
}

// round 12
// speedup vs baseline: 1.1081x; 1.1081x over previous
#include <cuda_runtime.h>
#include <cuda_bf16.h>

#define BATCH 8
#define H 512
#define W 512
#define KS 5
#define PAD 2

#define TX 32
#define TY 8
#define PY 2
#define OTY (TY * PY)       // 16 output rows per block
#define SW (TX + 2*PAD)     // 36
#define SH (OTY + 2*PAD)    // 20
#define TILE_N (SH * SW)    // 720
#define NTHREADS (TX * TY)  // 256

#define CHUNKS 64           // phase-1 minmax blocks per batch

__device__ float g_pmn[BATCH * CHUNKS];
__device__ float g_pmx[BATCH * CHUNKS];

// ---------------- Kernel A: per-chunk partial min/max (full-chip) ----------------
__global__ __launch_bounds__(256) void minmax_partial_kernel(const float* __restrict__ cm) {
    const int b = blockIdx.y;
    const int c = blockIdx.x;
    const float4* p = reinterpret_cast<const float4*>(cm) + ((size_t)b * (H * W / 4)) + (size_t)c * 1024;

    float mn = 1e30f, mx = -1e30f;
    #pragma unroll
    for (int i = 0; i < 4; ++i) {
        float4 v = p[threadIdx.x + i * 256];
        mn = fminf(mn, fminf(fminf(v.x, v.y), fminf(v.z, v.w)));
        mx = fmaxf(mx, fmaxf(fmaxf(v.x, v.y), fmaxf(v.z, v.w)));
    }
    #pragma unroll
    for (int o = 16; o; o >>= 1) {
        mn = fminf(mn, __shfl_xor_sync(0xFFFFFFFFu, mn, o));
        mx = fmaxf(mx, __shfl_xor_sync(0xFFFFFFFFu, mx, o));
    }
    __shared__ float smn[8], smx[8];
    const int wid = threadIdx.x >> 5, lid = threadIdx.x & 31;
    if (lid == 0) { smn[wid] = mn; smx[wid] = mx; }
    __syncthreads();
    if (threadIdx.x == 0) {
        #pragma unroll
        for (int i = 1; i < 8; ++i) { mn = fminf(mn, smn[i]); mx = fmaxf(mx, smx[i]); }
        g_pmn[b * CHUNKS + c] = mn;
        g_pmx[b * CHUNKS + c] = mx;
    }
}

// ---------------- Kernel B: pipelined sampler (loads hoisted over conv only) ----------------
__global__ __launch_bounds__(NTHREADS) void sampler_kernel(
    const float* __restrict__ cm,
    const float* __restrict__ rnd,
    const float* __restrict__ kern,
    float* __restrict__ coords,   // [B,512,512,4,2]
    float* __restrict__ weights,  // [B,512,512,4]
    float* __restrict__ density)  // [B,1,512,512]
{
    __shared__ float tile[SH][SW];
    __shared__ float kw[KS * KS];
    __shared__ float red_mn[CHUNKS], red_mx[CHUNKS];
    __shared__ float s_mn, s_sc;

    const int b   = blockIdx.z;
    const int tid = threadIdx.y * TX + threadIdx.x;

    const int x   = blockIdx.x * TX + threadIdx.x;
    const int ty2 = threadIdx.y * PY;
    const int y   = blockIdx.y * OTY + ty2;

    // ---------- contrast tile prefetch (registers, 3 values) ----------
    const int x0 = blockIdx.x * TX - PAD;
    const int y0 = blockIdx.y * OTY - PAD;
    const float* cmb = cm + (size_t)b * H * W;

    float pre[3];
    bool  pok[3];
    #pragma unroll
    for (int t = 0; t < 3; ++t) {
        const int i  = tid + t * NTHREADS;
        const int ly = i / SW, lx = i - ly * SW;
        const int gy = y0 + ly, gx = x0 + lx;
        pok[t] = (i < TILE_N) && ((unsigned)gy < H) && ((unsigned)gx < W);
        pre[t] = pok[t] ? cmb[gy * W + gx] : 0.0f;
    }

    // partials + kernel weights (small L2 loads)
    if (tid < CHUNKS) {
        red_mn[tid] = g_pmn[b * CHUNKS + tid];
        red_mx[tid] = g_pmx[b * CHUNKS + tid];
    } else if (tid < CHUNKS + KS * KS) {
        kw[tid - CHUNKS] = kern[tid - CHUNKS];
    }
    __syncthreads();

    // ---------- Phase 1: reduce partials to (mn, sc) ----------
    if (tid < 64) {
        const int lid = tid & 31;
        if (tid < 32) {
            float v = fminf(red_mn[lid], red_mn[lid + 32]);
            #pragma unroll
            for (int o = 16; o; o >>= 1) v = fminf(v, __shfl_xor_sync(0xFFFFFFFFu, v, o));
            if (lid == 0) s_mn = v;
        } else {
            float v = fmaxf(red_mx[lid], red_mx[lid + 32]);
            #pragma unroll
            for (int o = 16; o; o >>= 1) v = fmaxf(v, __shfl_xor_sync(0xFFFFFFFFu, v, o));
            if (lid == 0) red_mx[0] = v;
        }
    }
    __syncthreads();
    if (tid == 0) {
        const float rng = red_mx[0] - s_mn;
        s_sc = (rng > 0.0f) ? (1.0f / rng) : 0.0f;
    }
    __syncthreads();

    const float mn = s_mn;
    const float sc = s_sc;

    // ---------- Phase 2: normalize prefetched tile into smem ----------
    #pragma unroll
    for (int t = 0; t < 3; ++t) {
        const int i = tid + t * NTHREADS;
        if (i < TILE_N) {
            const int ly = i / SW, lx = i - ly * SW;
            tile[ly][lx] = pok[t] ? (pre[t] - mn) * sc : 0.0f;
        }
    }
    __syncthreads();

    // ---------- rnd loads issued HERE: overlap the conv, short register lifetime ----------
    const size_t pix0 = ((size_t)b * H + y) * W + x;
    const size_t pix1 = pix0 + W;
    const float4* rp0 = reinterpret_cast<const float4*>(rnd + pix0 * 8);
    const float4* rp1 = reinterpret_cast<const float4*>(rnd + pix1 * 8);
    float4 ra0 = __ldcs(rp0 + 0);
    float4 ra1 = __ldcs(rp0 + 1);
    float4 rb0 = __ldcs(rp1 + 0);
    float4 rb1 = __ldcs(rp1 + 1);

    // ---------- Phase 3: 5x5 conv, two adjacent rows, order-preserving ----------
    float acc0 = 0.0f, acc1 = 0.0f;
    #pragma unroll
    for (int r = 0; r < KS + 1; ++r) {
        float t0 = tile[ty2 + r][threadIdx.x + 0];
        float t1 = tile[ty2 + r][threadIdx.x + 1];
        float t2 = tile[ty2 + r][threadIdx.x + 2];
        float t3 = tile[ty2 + r][threadIdx.x + 3];
        float t4 = tile[ty2 + r][threadIdx.x + 4];
        if (r < KS) {
            acc0 = fmaf(kw[r * KS + 0], t0, acc0);
            acc0 = fmaf(kw[r * KS + 1], t1, acc0);
            acc0 = fmaf(kw[r * KS + 2], t2, acc0);
            acc0 = fmaf(kw[r * KS + 3], t3, acc0);
            acc0 = fmaf(kw[r * KS + 4], t4, acc0);
        }
        if (r > 0) {
            acc1 = fmaf(kw[(r - 1) * KS + 0], t0, acc1);
            acc1 = fmaf(kw[(r - 1) * KS + 1], t1, acc1);
            acc1 = fmaf(kw[(r - 1) * KS + 2], t2, acc1);
            acc1 = fmaf(kw[(r - 1) * KS + 3], t3, acc1);
            acc1 = fmaf(kw[(r - 1) * KS + 4], t4, acc1);
        }
    }

    // ---------- Phase 4: outputs ----------
    const float step = 2.0f / 511.0f;
    const float bx = fmaf((float)x, step, -1.0f);

    #pragma unroll
    for (int p = 0; p < PY; ++p) {
        const float acc = (p == 0) ? acc0 : acc1;
        const int   yy  = y + p;
        const float4 r0 = (p == 0) ? ra0 : rb0;
        const float4 r1 = (p == 0) ? ra1 : rb1;

        const float d   = fmaf(0.9f, sqrtf(acc), 0.1f);
        const int   ns  = (d > 0.7f) ? 4 : ((d > 0.4f) ? 2 : 1);
        const float by  = fmaf((float)yy, step, -1.0f);
        const float osc = (ns > 1) ? (2.0f / 512.0f * 0.8f) : 0.0f;

        const size_t pix = (p == 0) ? pix0 : pix1;

        float4 c0, c1;
        c0.x = fmaf(r0.x - 0.5f, osc, by);
        c0.y = fmaf(r0.y - 0.5f, osc, bx);
        c0.z = fmaf(r0.z - 0.5f, osc, by);
        c0.w = fmaf(r0.w - 0.5f, osc, bx);
        c1.x = fmaf(r1.x - 0.5f, osc, by);
        c1.y = fmaf(r1.y - 0.5f, osc, bx);
        c1.z = fmaf(r1.z - 0.5f, osc, by);
        c1.w = fmaf(r1.w - 0.5f, osc, bx);

        float4* cout = reinterpret_cast<float4*>(coords + pix * 8);
        cout[0] = c0;
        cout[1] = c1;

        const float wv = d / (float)ns;
        float4 wq;
        wq.x = wv;
        wq.y = (ns > 1) ? wv : 0.0f;
        wq.z = (ns > 2) ? wv : 0.0f;
        wq.w = (ns > 2) ? wv : 0.0f;
        reinterpret_cast<float4*>(weights + pix * 4)[0] = wq;

        density[pix] = d;
    }
}

extern "C" void kernel_launch(void* const* d_in, const int* in_sizes, int n_in,
                              void* d_out, int out_size) {
    const float* cm   = (const float*)d_in[0];  // [8,1,512,512]
    const float* rnd  = (const float*)d_in[1];  // [8,512,512,4,2]
    const float* kern = (const float*)d_in[2];  // [1,1,5,5]

    float* out = (float*)d_out;
    float* coords  = out;                                   // 16777216
    float* weights = out + (size_t)BATCH * H * W * 8;       //  8388608
    float* density = weights + (size_t)BATCH * H * W * 4;   //  2097152

    dim3 agrd(CHUNKS, BATCH, 1);
    minmax_partial_kernel<<<agrd, 256>>>(cm);

    dim3 blk(TX, TY, 1);
    dim3 grd(W / TX, H / OTY, BATCH);
    sampler_kernel<<<grd, blk>>>(cm, rnd, kern, coords, weights, density);
}